// round 3
// baseline (speedup 1.0000x reference)
#include <cuda_runtime.h>
#include <cuda_bf16.h>

#define N_NODES 100000
#define N_EDGES 3200000
#define H 128
#define N_GRAPHS 128
#define N_CLASSES 10
#define EPSBN 1e-5f

// ---------------- device scratch (static, no allocation) ----------------
__device__ int   g_deg[N_NODES];
__device__ float g_dinv[N_NODES];
__device__ float g_acc1[N_NODES];
__device__ float g_h1[(size_t)N_NODES * H];                    // post-relu, pre-BN layer1
__device__ __align__(16) float g_z[(size_t)N_NODES * H];       // hn1 @ Wc2
__device__ float g_lin2[(size_t)N_NODES * H];                  // hn1 @ Wl2
__device__ __align__(16) float g_acc2[(size_t)N_NODES * H];    // scatter accumulator
__device__ float g_h2[(size_t)N_NODES * H];                    // pre-BN layer2
__device__ float g_bn1[2 * H];                                 // sum, sumsq
__device__ float g_bn2[2 * H];
__device__ float g_s1[H], g_t1[H], g_s2[H], g_t2[H];
__device__ int   g_gcnt[N_GRAPHS];
__device__ int   g_goff[N_GRAPHS + 1];

// ---------------- kernels ----------------

__global__ void k_deg(const int* __restrict__ dst) {
    int e = blockIdx.x * blockDim.x + threadIdx.x;
    if (e < N_EDGES) atomicAdd(&g_deg[dst[e]], 1);
}

__global__ void k_dinv() {
    int i = blockIdx.x * blockDim.x + threadIdx.x;
    if (i < N_NODES) g_dinv[i] = rsqrtf((float)(g_deg[i] + 1));
}

// scalar layer-1 scatter: acc1[d] += dinv[s] * x[s]
__global__ void k_scatter1(const int* __restrict__ src,
                           const int* __restrict__ dst,
                           const float* __restrict__ x) {
    int e = blockIdx.x * blockDim.x + threadIdx.x;
    if (e >= N_EDGES) return;
    int s = src[e];
    int d = dst[e];
    atomicAdd(&g_acc1[d], g_dinv[s] * x[s]);
}

// layer1 node transform + BN1 partial stats. block = 128 threads (one per feature)
#define NPB 128
__global__ void __launch_bounds__(H) k_layer1(const float* __restrict__ x,
                                              const float* __restrict__ Wc1,
                                              const float* __restrict__ bc1,
                                              const float* __restrict__ Wl1,
                                              const float* __restrict__ bl1) {
    int f = threadIdx.x;
    float wc = Wc1[f], wl = Wl1[f], b = bc1[f] + bl1[f];
    float sum = 0.f, ssq = 0.f;
    int i0 = blockIdx.x * NPB;
    for (int r = 0; r < NPB; r++) {
        int i = i0 + r;
        if (i >= N_NODES) break;
        float di = g_dinv[i];
        float xi = x[i];
        float a = di * g_acc1[i] + di * di * xi;     // conv pre-bias aggregate
        float h = fmaf(a, wc, fmaf(xi, wl, b));
        h = fmaxf(h, 0.f);                            // relu
        g_h1[(size_t)i * H + f] = h;
        sum += h;
        ssq += h * h;
    }
    atomicAdd(&g_bn1[f], sum);
    atomicAdd(&g_bn1[H + f], ssq);
}

__global__ void k_bnfin(const float* __restrict__ sums,
                        const float* __restrict__ gamma,
                        const float* __restrict__ beta,
                        float* __restrict__ s_out, float* __restrict__ t_out) {
    int f = threadIdx.x;
    float inv_n = 1.0f / (float)N_NODES;
    float mu = sums[f] * inv_n;
    float var = sums[H + f] * inv_n - mu * mu;
    float s = gamma[f] * rsqrtf(var + EPSBN);
    s_out[f] = s;
    t_out[f] = beta[f] - mu * s;
}

// fused GEMM: hn1 (= h1*s1+t1) @ Wc2 -> z ; hn1 @ Wl2 -> lin2
// block: 128 threads, 32 nodes per block. 100000/32 = 3125 blocks exactly.
__global__ void __launch_bounds__(H) k_gemm(const float* __restrict__ Wc2,
                                            const float* __restrict__ Wl2) {
    __shared__ float sA[32][H];
    int t = threadIdx.x;
    int i0 = blockIdx.x * 32;
    float sl = g_s1[t], tl = g_t1[t];
#pragma unroll 4
    for (int j = 0; j < 32; j++)
        sA[j][t] = fmaf(g_h1[(size_t)(i0 + j) * H + t], sl, tl);
    __syncthreads();

    float accA[32], accB[32];
#pragma unroll
    for (int r = 0; r < 32; r++) { accA[r] = 0.f; accB[r] = 0.f; }

    for (int k = 0; k < H; k++) {
        float w0 = Wc2[k * H + t];
        float w1 = Wl2[k * H + t];
#pragma unroll
        for (int r = 0; r < 32; r++) {
            float a = sA[r][k];
            accA[r] = fmaf(a, w0, accA[r]);
            accB[r] = fmaf(a, w1, accB[r]);
        }
    }
#pragma unroll 4
    for (int r = 0; r < 32; r++) {
        g_z[(size_t)(i0 + r) * H + t]    = accA[r];
        g_lin2[(size_t)(i0 + r) * H + t] = accB[r];
    }
}

// layer-2 128-wide scatter: warp per edge, lane handles 4 floats (float4)
// acc2[d,:] += dinv[s] * z[s,:]   via vector reduction (no return)
__global__ void k_scatter2(const int* __restrict__ src,
                           const int* __restrict__ dst) {
    int w = (blockIdx.x * blockDim.x + threadIdx.x) >> 5;
    int lane = threadIdx.x & 31;
    if (w >= N_EDGES) return;
    int s = __ldg(&src[w]);
    int d = __ldg(&dst[w]);
    float di = g_dinv[s];
    const float4* zp = (const float4*)(g_z + (size_t)s * H);
    float4 v = zp[lane];
    v.x *= di; v.y *= di; v.z *= di; v.w *= di;
    float* ap = g_acc2 + (size_t)d * H + lane * 4;
    asm volatile("red.global.add.v4.f32 [%0], {%1,%2,%3,%4};"
                 :: "l"(ap), "f"(v.x), "f"(v.y), "f"(v.z), "f"(v.w) : "memory");
}

// combine conv2 + lin2 + biases -> h2, with BN2 partial stats
__global__ void __launch_bounds__(H) k_combine(const float* __restrict__ bc2,
                                               const float* __restrict__ bl2) {
    int f = threadIdx.x;
    float b = bc2[f] + bl2[f];
    float sum = 0.f, ssq = 0.f;
    int i0 = blockIdx.x * NPB;
    for (int r = 0; r < NPB; r++) {
        int i = i0 + r;
        if (i >= N_NODES) break;
        float di = g_dinv[i];
        size_t off = (size_t)i * H + f;
        float conv = di * (g_acc2[off] + di * g_z[off]);   // edges + self loop
        float h = conv + g_lin2[off] + b;
        g_h2[off] = h;
        sum += h;
        ssq += h * h;
    }
    atomicAdd(&g_bn2[f], sum);
    atomicAdd(&g_bn2[H + f], ssq);
}

__global__ void k_gcnt(const int* __restrict__ batch) {
    __shared__ int sh[N_GRAPHS];
    if (threadIdx.x < N_GRAPHS) sh[threadIdx.x] = 0;
    __syncthreads();
    int i = blockIdx.x * blockDim.x + threadIdx.x;
    if (i < N_NODES) atomicAdd(&sh[batch[i]], 1);
    __syncthreads();
    if (threadIdx.x < N_GRAPHS && sh[threadIdx.x])
        atomicAdd(&g_gcnt[threadIdx.x], sh[threadIdx.x]);
}

__global__ void k_prefix() {
    if (threadIdx.x == 0) {
        int acc = 0;
        for (int g = 0; g < N_GRAPHS; g++) { g_goff[g] = acc; acc += g_gcnt[g]; }
        g_goff[N_GRAPHS] = acc;
    }
}

// per-graph mean pool (BN2 affine commutes with the mean) + classifier head
__global__ void __launch_bounds__(H) k_pool(const float* __restrict__ W3,
                                            const float* __restrict__ b3,
                                            float* __restrict__ out) {
    __shared__ float sp[H];
    int g = blockIdx.x;
    int f = threadIdx.x;
    int i0 = g_goff[g], i1 = g_goff[g + 1];
    float acc = 0.f;
    for (int i = i0; i < i1; i++) acc += g_h2[(size_t)i * H + f];
    int cnt = i1 - i0;
    float pooled;
    if (cnt > 0)
        pooled = fmaf(acc / (float)cnt, g_s2[f], g_t2[f]);
    else
        pooled = 0.f;
    sp[f] = pooled;
    __syncthreads();
    if (f < N_CLASSES) {
        float o = b3[f];
        for (int k = 0; k < H; k++) o = fmaf(sp[k], W3[k * N_CLASSES + f], o);
        out[g * N_CLASSES + f] = o;
    }
}

// ---------------- host launch ----------------
extern "C" void kernel_launch(void* const* d_in, const int* in_sizes, int n_in,
                              void* d_out, int out_size) {
    const float* x   = (const float*)d_in[0];
    const int*   ei  = (const int*)d_in[1];      // int32 (JAX x64 disabled)
    const int*   bat = (const int*)d_in[2];
    const float* Wc1 = (const float*)d_in[3];
    const float* bc1 = (const float*)d_in[4];
    const float* Wl1 = (const float*)d_in[5];
    const float* bl1 = (const float*)d_in[6];
    const float* g1  = (const float*)d_in[7];
    const float* be1 = (const float*)d_in[8];
    const float* Wc2 = (const float*)d_in[9];
    const float* bc2 = (const float*)d_in[10];
    const float* Wl2 = (const float*)d_in[11];
    const float* bl2 = (const float*)d_in[12];
    const float* g2  = (const float*)d_in[13];
    const float* be2 = (const float*)d_in[14];
    const float* W3  = (const float*)d_in[15];
    const float* b3  = (const float*)d_in[16];
    float* out = (float*)d_out;

    const int* src = ei;
    const int* dst = ei + N_EDGES;

    void *p_deg, *p_acc1, *p_acc2, *p_bn1, *p_bn2, *p_gcnt;
    void *p_s1, *p_t1, *p_s2, *p_t2;
    cudaGetSymbolAddress(&p_deg,  g_deg);
    cudaGetSymbolAddress(&p_acc1, g_acc1);
    cudaGetSymbolAddress(&p_acc2, g_acc2);
    cudaGetSymbolAddress(&p_bn1,  g_bn1);
    cudaGetSymbolAddress(&p_bn2,  g_bn2);
    cudaGetSymbolAddress(&p_gcnt, g_gcnt);
    cudaGetSymbolAddress(&p_s1, g_s1);
    cudaGetSymbolAddress(&p_t1, g_t1);
    cudaGetSymbolAddress(&p_s2, g_s2);
    cudaGetSymbolAddress(&p_t2, g_t2);

    cudaMemsetAsync(p_deg,  0, N_NODES * sizeof(int), 0);
    cudaMemsetAsync(p_acc1, 0, N_NODES * sizeof(float), 0);
    cudaMemsetAsync(p_acc2, 0, (size_t)N_NODES * H * sizeof(float), 0);
    cudaMemsetAsync(p_bn1,  0, 2 * H * sizeof(float), 0);
    cudaMemsetAsync(p_bn2,  0, 2 * H * sizeof(float), 0);
    cudaMemsetAsync(p_gcnt, 0, N_GRAPHS * sizeof(int), 0);

    k_deg<<<(N_EDGES + 255) / 256, 256>>>(dst);
    k_dinv<<<(N_NODES + 255) / 256, 256>>>();
    k_scatter1<<<(N_EDGES + 255) / 256, 256>>>(src, dst, x);
    k_layer1<<<(N_NODES + NPB - 1) / NPB, H>>>(x, Wc1, bc1, Wl1, bl1);
    k_bnfin<<<1, H>>>((const float*)p_bn1, g1, be1, (float*)p_s1, (float*)p_t1);
    k_gemm<<<N_NODES / 32, H>>>(Wc2, Wl2);
    k_scatter2<<<((size_t)N_EDGES * 32 + 255) / 256, 256>>>(src, dst);
    k_combine<<<(N_NODES + NPB - 1) / NPB, H>>>(bc2, bl2);
    k_bnfin<<<1, H>>>((const float*)p_bn2, g2, be2, (float*)p_s2, (float*)p_t2);
    k_gcnt<<<(N_NODES + 255) / 256, 256>>>(bat);
    k_prefix<<<1, 32>>>();
    k_pool<<<N_GRAPHS, H>>>(W3, b3, out);
}

// round 5
// speedup vs baseline: 1.0016x; 1.0016x over previous
#include <cuda_runtime.h>
#include <cuda_bf16.h>

#define N_NODES 100000
#define N_EDGES 3200000
#define H 128
#define N_GRAPHS 128
#define N_CLASSES 10
#define EPSBN 1e-5f

// ---------------- device scratch (static, no allocation) ----------------
__device__ int   g_deg[N_NODES];
__device__ int   g_off[N_NODES + 1];
__device__ int   g_cur[N_NODES];
__device__ int   g_csrc[N_EDGES];                               // CSR-by-dst src ids
__device__ float g_dinv[N_NODES];
__device__ float g_acc1[N_NODES];                               // Σ dinv[s]*x[s]
__device__ float g_sdin[N_NODES];                               // Σ dinv[s]
__device__ __align__(16) float g_h1[(size_t)N_NODES * H];       // post-relu, pre-BN layer1
__device__ __align__(16) float g_agg[(size_t)N_NODES * H];      // Σ dinv[s]*h1[s]
__device__ float g_bn1[2 * H];                                  // sum, sumsq
__device__ float g_bn2[2 * H];
__device__ float g_s1[H], g_t1[H], g_s2[H], g_t2[H];
__device__ float g_pool[N_GRAPHS * H];                          // raw h2 per-graph sums
__device__ int   g_gcnt[N_GRAPHS];

// ---------------- kernels ----------------

__global__ void k_deg(const int* __restrict__ dst) {
    int e = blockIdx.x * blockDim.x + threadIdx.x;
    if (e < N_EDGES) atomicAdd(&g_deg[dst[e]], 1);
}

// single-block exclusive scan of deg -> off (and cur copy)
__global__ void __launch_bounds__(1024) k_scan() {
    __shared__ int ssum[1024];
    int t = threadIdx.x;
    const int CH = (N_NODES + 1023) / 1024;     // 98
    int i0 = t * CH, i1 = min(i0 + CH, N_NODES);
    int s = 0;
    for (int i = i0; i < i1; i++) s += g_deg[i];
    ssum[t] = s;
    __syncthreads();
    for (int off = 1; off < 1024; off <<= 1) {
        int v = (t >= off) ? ssum[t - off] : 0;
        __syncthreads();
        ssum[t] += v;
        __syncthreads();
    }
    int run = ssum[t] - s;                       // exclusive prefix
    for (int i = i0; i < i1; i++) {
        g_off[i] = run; g_cur[i] = run;
        run += g_deg[i];
    }
    if (t == 1023) g_off[N_NODES] = ssum[1023];
}

__global__ void k_fill(const int* __restrict__ src, const int* __restrict__ dst) {
    int e = blockIdx.x * blockDim.x + threadIdx.x;
    if (e >= N_EDGES) return;
    int slot = atomicAdd(&g_cur[dst[e]], 1);
    g_csrc[slot] = src[e];
}

__global__ void k_dinv() {
    int i = blockIdx.x * blockDim.x + threadIdx.x;
    if (i < N_NODES) g_dinv[i] = rsqrtf((float)(g_deg[i] + 1));
}

// warp per node: acc1[d] = Σ dinv[s]*x[s], sdin[d] = Σ dinv[s]   (no atomics)
__global__ void k_gather1(const float* __restrict__ x) {
    int node = (blockIdx.x * blockDim.x + threadIdx.x) >> 5;
    int lane = threadIdx.x & 31;
    if (node >= N_NODES) return;
    int e0 = g_off[node], e1 = g_off[node + 1];
    float a = 0.f, sd = 0.f;
    for (int e = e0 + lane; e < e1; e += 32) {
        int s = g_csrc[e];
        float di = g_dinv[s];
        a = fmaf(di, x[s], a);
        sd += di;
    }
#pragma unroll
    for (int o = 16; o > 0; o >>= 1) {
        a  += __shfl_down_sync(0xffffffffu, a, o);
        sd += __shfl_down_sync(0xffffffffu, sd, o);
    }
    if (lane == 0) { g_acc1[node] = a; g_sdin[node] = sd; }
}

// layer1 node transform + BN1 partial stats. block = 128 threads (one per feature)
#define NPB 128
__global__ void __launch_bounds__(H) k_layer1(const float* __restrict__ x,
                                              const float* __restrict__ Wc1,
                                              const float* __restrict__ bc1,
                                              const float* __restrict__ Wl1,
                                              const float* __restrict__ bl1) {
    int f = threadIdx.x;
    float wc = Wc1[f], wl = Wl1[f], b = bc1[f] + bl1[f];
    float sum = 0.f, ssq = 0.f;
    int i0 = blockIdx.x * NPB;
    for (int r = 0; r < NPB; r++) {
        int i = i0 + r;
        if (i >= N_NODES) break;
        float di = g_dinv[i];
        float xi = x[i];
        float a = di * g_acc1[i] + di * di * xi;
        float h = fmaf(a, wc, fmaf(xi, wl, b));
        h = fmaxf(h, 0.f);
        g_h1[(size_t)i * H + f] = h;
        sum += h;
        ssq += h * h;
    }
    atomicAdd(&g_bn1[f], sum);
    atomicAdd(&g_bn1[H + f], ssq);
}

__global__ void k_bnfin(const float* __restrict__ sums,
                        const float* __restrict__ gamma,
                        const float* __restrict__ beta,
                        float* __restrict__ s_out, float* __restrict__ t_out) {
    int f = threadIdx.x;
    float inv_n = 1.0f / (float)N_NODES;
    float mu = sums[f] * inv_n;
    float var = sums[H + f] * inv_n - mu * mu;
    float s = gamma[f] * rsqrtf(var + EPSBN);
    s_out[f] = s;
    t_out[f] = beta[f] - mu * s;
}

// warp per node: agg[d,:] = Σ dinv[s] * h1[s,:]   (raw h1; BN affine folded later)
__global__ void k_gather2() {
    int node = (blockIdx.x * blockDim.x + threadIdx.x) >> 5;
    int lane = threadIdx.x & 31;
    if (node >= N_NODES) return;
    int e0 = g_off[node], e1 = g_off[node + 1];
    float4 acc = make_float4(0.f, 0.f, 0.f, 0.f);
    for (int e = e0; e < e1; e++) {
        int s = __ldg(&g_csrc[e]);
        float di = __ldg(&g_dinv[s]);
        float4 v = *(const float4*)(g_h1 + (size_t)s * H + lane * 4);
        acc.x = fmaf(di, v.x, acc.x);
        acc.y = fmaf(di, v.y, acc.y);
        acc.z = fmaf(di, v.z, acc.z);
        acc.w = fmaf(di, v.w, acc.w);
    }
    *(float4*)(g_agg + (size_t)node * H + lane * 4) = acc;
}

// fused layer-2: h2 = A1@Wc2 + A2@Wl2 + b, with BN2 stats + per-graph pool sums.
// A2 = hn1 = h1*s1+t1 ; A1 = dinv*(s1*agg + t1*sdin + dinv*hn1)
// block: 128 threads, 32 nodes. h2 never hits memory.
__global__ void __launch_bounds__(H) k_gemm2(const float* __restrict__ Wc2,
                                             const float* __restrict__ Wl2,
                                             const float* __restrict__ bc2,
                                             const float* __restrict__ bl2,
                                             const int* __restrict__ bat) {
    __shared__ float sA1[32][H];
    __shared__ float sA2[32][H];
    __shared__ int sb[32];
    int t = threadIdx.x;
    int i0 = blockIdx.x * 32;
    float s1 = g_s1[t], t1 = g_t1[t];
    if (t < 32) sb[t] = bat[i0 + t];
#pragma unroll 4
    for (int j = 0; j < 32; j++) {
        int i = i0 + j;
        float hn = fmaf(g_h1[(size_t)i * H + t], s1, t1);
        float di = g_dinv[i];
        float a1 = di * (fmaf(s1, g_agg[(size_t)i * H + t], t1 * g_sdin[i]) + di * hn);
        sA1[j][t] = a1;
        sA2[j][t] = hn;
    }
    __syncthreads();

    float accA[32], accB[32];
#pragma unroll
    for (int r = 0; r < 32; r++) { accA[r] = 0.f; accB[r] = 0.f; }

    for (int k = 0; k < H; k++) {
        float w0 = Wc2[k * H + t];
        float w1 = Wl2[k * H + t];
#pragma unroll
        for (int r = 0; r < 32; r++) {
            accA[r] = fmaf(sA1[r][k], w0, accA[r]);
            accB[r] = fmaf(sA2[r][k], w1, accB[r]);
        }
    }

    float b = bc2[t] + bl2[t];
    float sum = 0.f, ssq = 0.f;
    float seg = 0.f;
    int cg = sb[0];
#pragma unroll
    for (int r = 0; r < 32; r++) {
        float v = accA[r] + accB[r] + b;      // h2 value
        sum += v;
        ssq += v * v;
        int gId = sb[r];
        if (gId != cg) {
            atomicAdd(&g_pool[cg * H + t], seg);
            seg = 0.f;
            cg = gId;
        }
        seg += v;
    }
    atomicAdd(&g_pool[cg * H + t], seg);
    atomicAdd(&g_bn2[t], sum);
    atomicAdd(&g_bn2[H + t], ssq);
}

__global__ void k_gcnt(const int* __restrict__ batch) {
    __shared__ int sh[N_GRAPHS];
    if (threadIdx.x < N_GRAPHS) sh[threadIdx.x] = 0;
    __syncthreads();
    int i = blockIdx.x * blockDim.x + threadIdx.x;
    if (i < N_NODES) atomicAdd(&sh[batch[i]], 1);
    __syncthreads();
    if (threadIdx.x < N_GRAPHS && sh[threadIdx.x])
        atomicAdd(&g_gcnt[threadIdx.x], sh[threadIdx.x]);
}

// pooled mean (BN2 affine commutes with mean) + classifier head
__global__ void __launch_bounds__(H) k_head(const float* __restrict__ W3,
                                            const float* __restrict__ b3,
                                            float* __restrict__ out) {
    __shared__ float sp[H];
    int g = blockIdx.x;
    int f = threadIdx.x;
    int cnt = g_gcnt[g];
    float pooled = 0.f;
    if (cnt > 0)
        pooled = fmaf(g_pool[g * H + f] / (float)cnt, g_s2[f], g_t2[f]);
    sp[f] = pooled;
    __syncthreads();
    if (f < N_CLASSES) {
        float o = b3[f];
#pragma unroll 8
        for (int k = 0; k < H; k++) o = fmaf(sp[k], W3[k * N_CLASSES + f], o);
        out[g * N_CLASSES + f] = o;
    }
}

// ---------------- host launch ----------------
extern "C" void kernel_launch(void* const* d_in, const int* in_sizes, int n_in,
                              void* d_out, int out_size) {
    const float* x   = (const float*)d_in[0];
    const int*   ei  = (const int*)d_in[1];
    const int*   bat = (const int*)d_in[2];
    const float* Wc1 = (const float*)d_in[3];
    const float* bc1 = (const float*)d_in[4];
    const float* Wl1 = (const float*)d_in[5];
    const float* bl1 = (const float*)d_in[6];
    const float* g1  = (const float*)d_in[7];
    const float* be1 = (const float*)d_in[8];
    const float* Wc2 = (const float*)d_in[9];
    const float* bc2 = (const float*)d_in[10];
    const float* Wl2 = (const float*)d_in[11];
    const float* bl2 = (const float*)d_in[12];
    const float* g2  = (const float*)d_in[13];
    const float* be2 = (const float*)d_in[14];
    const float* W3  = (const float*)d_in[15];
    const float* b3  = (const float*)d_in[16];
    float* out = (float*)d_out;

    const int* src = ei;
    const int* dst = ei + N_EDGES;

    void *p_deg, *p_bn1, *p_bn2, *p_gcnt, *p_pool;
    void *p_s1, *p_t1, *p_s2, *p_t2;
    cudaGetSymbolAddress(&p_deg,  g_deg);
    cudaGetSymbolAddress(&p_bn1,  g_bn1);
    cudaGetSymbolAddress(&p_bn2,  g_bn2);
    cudaGetSymbolAddress(&p_gcnt, g_gcnt);
    cudaGetSymbolAddress(&p_pool, g_pool);
    cudaGetSymbolAddress(&p_s1, g_s1);
    cudaGetSymbolAddress(&p_t1, g_t1);
    cudaGetSymbolAddress(&p_s2, g_s2);
    cudaGetSymbolAddress(&p_t2, g_t2);

    cudaMemsetAsync(p_deg,  0, N_NODES * sizeof(int), 0);
    cudaMemsetAsync(p_bn1,  0, 2 * H * sizeof(float), 0);
    cudaMemsetAsync(p_bn2,  0, 2 * H * sizeof(float), 0);
    cudaMemsetAsync(p_gcnt, 0, N_GRAPHS * sizeof(int), 0);
    cudaMemsetAsync(p_pool, 0, N_GRAPHS * H * sizeof(float), 0);

    k_deg<<<(N_EDGES + 255) / 256, 256>>>(dst);
    k_scan<<<1, 1024>>>();
    k_fill<<<(N_EDGES + 255) / 256, 256>>>(src, dst);
    k_dinv<<<(N_NODES + 255) / 256, 256>>>();
    k_gather1<<<((size_t)N_NODES * 32 + 255) / 256, 256>>>(x);
    k_layer1<<<(N_NODES + NPB - 1) / NPB, H>>>(x, Wc1, bc1, Wl1, bl1);
    k_bnfin<<<1, H>>>((const float*)p_bn1, g1, be1, (float*)p_s1, (float*)p_t1);
    k_gather2<<<((size_t)N_NODES * 32 + 255) / 256, 256>>>();
    k_gemm2<<<N_NODES / 32, H>>>(Wc2, Wl2, bc2, bl2, bat);
    k_bnfin<<<1, H>>>((const float*)p_bn2, g2, be2, (float*)p_s2, (float*)p_t2);
    k_gcnt<<<(N_NODES + 255) / 256, 256>>>(bat);
    k_head<<<N_GRAPHS, H>>>(W3, b3, out);
}

// round 7
// speedup vs baseline: 1.7241x; 1.7214x over previous
#include <cuda_runtime.h>
#include <cuda_bf16.h>
#include <cstdint>

#define N_NODES 100000
#define N_EDGES 3200000
#define H 128
#define N_GRAPHS 128
#define N_CLASSES 10
#define EPSBN 1e-5f
#define NCHUNK 98               // ceil(100000/1024)

// ---------------- device scratch (static, no allocation) ----------------
__device__ int   g_deg[N_NODES];
__device__ int   g_off[N_NODES + 1];
__device__ int   g_cur[N_NODES];
__device__ int   g_bsum[NCHUNK];
__device__ int   g_bpre[NCHUNK];
__device__ __align__(8) int2 g_edge[N_EDGES];                   // {src, bits(dinv[src])}
__device__ float g_dinv[N_NODES];
__device__ float g_acc1[N_NODES];                               // sum dinv[s]*x[s]
__device__ float g_sdin[N_NODES];                               // sum dinv[s]
__device__ __align__(16) float g_h1[(size_t)N_NODES * H];       // post-relu (fp32)
__device__ __align__(16) float g_agg[(size_t)N_NODES * H];      // sum dinv*h1 (fp32)
__device__ __align__(8) uint2 g_w2[128 * 128];                  // [n][kword]: {hi,lo} bf16x2
__device__ float g_bn1[2 * H];
__device__ float g_bn2[2 * H];
__device__ float g_s1[H], g_t1[H], g_s2[H], g_t2[H];
__device__ float g_pool[N_GRAPHS * H];
__device__ int   g_gcnt[N_GRAPHS];

// ---------------- CSR build ----------------

__global__ void k_deg(const int* __restrict__ dst) {
    int e = blockIdx.x * blockDim.x + threadIdx.x;
    if (e < N_EDGES) atomicAdd(&g_deg[dst[e]], 1);
}

__global__ void __launch_bounds__(1024) k_chunksum() {
    __shared__ int ss[1024];
    int t = threadIdx.x;
    int i = blockIdx.x * 1024 + t;
    int v = (i < N_NODES) ? g_deg[i] : 0;
    ss[t] = v;
    __syncthreads();
    for (int o = 1; o < 1024; o <<= 1) {
        int u = (t >= o) ? ss[t - o] : 0;
        __syncthreads();
        ss[t] += u;
        __syncthreads();
    }
    if (i < N_NODES) g_off[i] = ss[t] - v;
    if (t == 1023) g_bsum[blockIdx.x] = ss[1023];
}

__global__ void __launch_bounds__(128) k_bscan() {
    __shared__ int ss[128];
    int t = threadIdx.x;
    int v = (t < NCHUNK) ? g_bsum[t] : 0;
    ss[t] = v;
    __syncthreads();
    for (int o = 1; o < 128; o <<= 1) {
        int u = (t >= o) ? ss[t - o] : 0;
        __syncthreads();
        ss[t] += u;
        __syncthreads();
    }
    if (t < NCHUNK) g_bpre[t] = ss[t] - v;
    if (t == NCHUNK - 1) g_off[N_NODES] = ss[t];
}

__global__ void __launch_bounds__(1024) k_finoff() {
    int i = blockIdx.x * 1024 + threadIdx.x;
    if (i < N_NODES) {
        int o = g_off[i] + g_bpre[blockIdx.x];
        g_off[i] = o;
        g_cur[i] = o;
    }
}

__global__ void k_dinv() {
    int i = blockIdx.x * blockDim.x + threadIdx.x;
    if (i < N_NODES) g_dinv[i] = rsqrtf((float)(g_deg[i] + 1));
}

__global__ void k_fill(const int* __restrict__ src, const int* __restrict__ dst) {
    int e = blockIdx.x * blockDim.x + threadIdx.x;
    if (e >= N_EDGES) return;
    int s = src[e];
    int slot = atomicAdd(&g_cur[dst[e]], 1);
    g_edge[slot] = make_int2(s, __float_as_int(g_dinv[s]));
}

// ---------------- layer 1 ----------------

__global__ void k_gather1(const float* __restrict__ x) {
    int node = (blockIdx.x * blockDim.x + threadIdx.x) >> 5;
    int lane = threadIdx.x & 31;
    if (node >= N_NODES) return;
    int e0 = g_off[node], e1 = g_off[node + 1];
    float a = 0.f, sd = 0.f;
    for (int e = e0 + lane; e < e1; e += 32) {
        int2 r = g_edge[e];
        float w = __int_as_float(r.y);
        a = fmaf(w, x[r.x], a);
        sd += w;
    }
#pragma unroll
    for (int o = 16; o > 0; o >>= 1) {
        a  += __shfl_down_sync(0xffffffffu, a, o);
        sd += __shfl_down_sync(0xffffffffu, sd, o);
    }
    if (lane == 0) { g_acc1[node] = a; g_sdin[node] = sd; }
}

#define NPB 128
__global__ void __launch_bounds__(H) k_layer1(const float* __restrict__ x,
                                              const float* __restrict__ Wc1,
                                              const float* __restrict__ bc1,
                                              const float* __restrict__ Wl1,
                                              const float* __restrict__ bl1) {
    int f = threadIdx.x;
    float wc = Wc1[f], wl = Wl1[f], b = bc1[f] + bl1[f];
    float sum = 0.f, ssq = 0.f;
    int i0 = blockIdx.x * NPB;
    for (int r = 0; r < NPB; r++) {
        int i = i0 + r;
        if (i >= N_NODES) break;
        float di = g_dinv[i];
        float xi = x[i];
        float a = di * g_acc1[i] + di * di * xi;
        float h = fmaf(a, wc, fmaf(xi, wl, b));
        h = fmaxf(h, 0.f);
        g_h1[(size_t)i * H + f] = h;
        sum += h;
        ssq += h * h;
    }
    atomicAdd(&g_bn1[f], sum);
    atomicAdd(&g_bn1[H + f], ssq);
}

__global__ void k_bnfin(const float* __restrict__ sums,
                        const float* __restrict__ gamma,
                        const float* __restrict__ beta,
                        float* __restrict__ s_out, float* __restrict__ t_out) {
    int f = threadIdx.x;
    float inv_n = 1.0f / (float)N_NODES;
    float mu = sums[f] * inv_n;
    float var = sums[H + f] * inv_n - mu * mu;
    float s = gamma[f] * rsqrtf(var + EPSBN);
    s_out[f] = s;
    t_out[f] = beta[f] - mu * s;
}

// ---------------- layer 2 aggregation (warp per node, fp32) ----------------

__global__ void k_gather2() {
    int node = (blockIdx.x * blockDim.x + threadIdx.x) >> 5;
    int lane = threadIdx.x & 31;
    if (node >= N_NODES) return;
    int e0 = g_off[node], e1 = g_off[node + 1];
    float4 acc = make_float4(0.f, 0.f, 0.f, 0.f);
    if (e0 < e1) {
        int2 rec = g_edge[e0];
        for (int e = e0; e < e1; e++) {
            int2 nrec = (e + 1 < e1) ? g_edge[e + 1] : rec;   // prefetch
            float w = __int_as_float(rec.y);
            float4 v = *(const float4*)(g_h1 + (size_t)rec.x * H + lane * 4);
            acc.x = fmaf(w, v.x, acc.x);
            acc.y = fmaf(w, v.y, acc.y);
            acc.z = fmaf(w, v.z, acc.z);
            acc.w = fmaf(w, v.w, acc.w);
            rec = nrec;
        }
    }
    *(float4*)(g_agg + (size_t)node * H + lane * 4) = acc;
}

// ---------------- W prep: interleaved bf16 hi/lo split ----------------

__device__ __forceinline__ uint32_t pack_bf2(__nv_bfloat16 a, __nv_bfloat16 b) {
    __nv_bfloat162 p; p.x = a; p.y = b;
    return *(uint32_t*)&p;
}

__global__ void k_wprep(const float* __restrict__ Wc2, const float* __restrict__ Wl2) {
    int idx = blockIdx.x * blockDim.x + threadIdx.x;   // 128 n * 128 kwords
    if (idx >= 128 * 128) return;
    int n = idx >> 7, kw = idx & 127;
    int k0 = kw * 2, k1 = kw * 2 + 1;
    float v0 = (k0 < 128) ? Wc2[k0 * 128 + n] : Wl2[(k0 - 128) * 128 + n];
    float v1 = (k1 < 128) ? Wc2[k1 * 128 + n] : Wl2[(k1 - 128) * 128 + n];
    __nv_bfloat16 h0 = __float2bfloat16_rn(v0);
    __nv_bfloat16 h1v = __float2bfloat16_rn(v1);
    __nv_bfloat16 l0 = __float2bfloat16_rn(v0 - __bfloat162float(h0));
    __nv_bfloat16 l1 = __float2bfloat16_rn(v1 - __bfloat162float(h1v));
    g_w2[n * 128 + kw] = make_uint2(pack_bf2(h0, h1v), pack_bf2(l0, l1));
}

// ---------------- fused layer-2 GEMM (split-bf16 mma) + BN2 + pool ----------------
// Block: 128 threads (4 warps as 2 M-pairs x 2 N-halves). Tile: 64 nodes x 128 feats.
// K=256 in 4 chunks of 64. A[:,0:128)=A1 (conv), [128:256)=A2 (hn1). C = A @ W^T.
// A split into bf16 hi+lo in smem; W hi/lo from global (L1-resident).

#define AST 36                     // A row stride in b32 (64 bf16 + pad)
#define HST 132                    // sH row stride in f32

#define MMA3(cc, ah, al, bh0, bh1, bl0, bl1)                                   \
    asm volatile("mma.sync.aligned.m16n8k16.row.col.f32.bf16.bf16.f32 "        \
        "{%0,%1,%2,%3}, {%4,%5,%6,%7}, {%8,%9}, {%0,%1,%2,%3};"                \
        : "+f"(cc[0]), "+f"(cc[1]), "+f"(cc[2]), "+f"(cc[3])                   \
        : "r"(ah[0]), "r"(ah[1]), "r"(ah[2]), "r"(ah[3]), "r"(bh0), "r"(bh1)); \
    asm volatile("mma.sync.aligned.m16n8k16.row.col.f32.bf16.bf16.f32 "        \
        "{%0,%1,%2,%3}, {%4,%5,%6,%7}, {%8,%9}, {%0,%1,%2,%3};"                \
        : "+f"(cc[0]), "+f"(cc[1]), "+f"(cc[2]), "+f"(cc[3])                   \
        : "r"(al[0]), "r"(al[1]), "r"(al[2]), "r"(al[3]), "r"(bh0), "r"(bh1)); \
    asm volatile("mma.sync.aligned.m16n8k16.row.col.f32.bf16.bf16.f32 "        \
        "{%0,%1,%2,%3}, {%4,%5,%6,%7}, {%8,%9}, {%0,%1,%2,%3};"                \
        : "+f"(cc[0]), "+f"(cc[1]), "+f"(cc[2]), "+f"(cc[3])                   \
        : "r"(ah[0]), "r"(ah[1]), "r"(ah[2]), "r"(ah[3]), "r"(bl0), "r"(bl1));

__global__ void __launch_bounds__(128) k_gemm2(const float* __restrict__ bc2,
                                               const float* __restrict__ bl2,
                                               const int* __restrict__ bat) {
    __shared__ __align__(16) char smem_raw[64 * HST * 4];       // 33792 B union
    uint32_t* sAhi = (uint32_t*)smem_raw;                       // [64][AST]
    uint32_t* sAlo = sAhi + 64 * AST;
    __nv_bfloat16* sAhi_b = (__nv_bfloat16*)sAhi;
    __nv_bfloat16* sAlo_b = (__nv_bfloat16*)sAlo;
    float* sH = (float*)smem_raw;                               // overlay after mma
    __shared__ float ss1[H], st1[H];
    __shared__ int sb[64];

    int tid = threadIdx.x;
    int lane = tid & 31;
    int warp = tid >> 5;
    int g = lane >> 2, tg = lane & 3;
    int wx = warp & 1, wy = warp >> 1;      // wx: N-half, wy: M-pair
    int i0 = blockIdx.x * 64;

    ss1[tid] = g_s1[tid];
    st1[tid] = g_t1[tid];
    if (tid < 64) {
        int i = i0 + tid;
        sb[tid] = (i < N_NODES) ? bat[i] : 0;
    }

    float c[2][8][4];
#pragma unroll
    for (int mi = 0; mi < 2; mi++)
#pragma unroll
        for (int jj = 0; jj < 8; jj++)
#pragma unroll
            for (int q = 0; q < 4; q++) c[mi][jj][q] = 0.f;

    for (int ch = 0; ch < 4; ch++) {
        int kc0 = ch * 64;
        __syncthreads();
        // stage A chunk, split hi/lo
        for (int idx = tid; idx < 64 * 64; idx += 128) {
            int r = idx >> 6, fc = idx & 63;
            int i = i0 + r;
            int f = kc0 + fc;
            float v = 0.f;
            if (i < N_NODES) {
                if (f < 128) {
                    float hn = fmaf(g_h1[(size_t)i * H + f], ss1[f], st1[f]);
                    float di = g_dinv[i];
                    v = di * (fmaf(ss1[f], g_agg[(size_t)i * H + f],
                                   st1[f] * g_sdin[i]) + di * hn);
                } else {
                    int ff = f - 128;
                    v = fmaf(g_h1[(size_t)i * H + ff], ss1[ff], st1[ff]);
                }
            }
            __nv_bfloat16 hi = __float2bfloat16_rn(v);
            sAhi_b[r * (AST * 2) + fc] = hi;
            sAlo_b[r * (AST * 2) + fc] = __float2bfloat16_rn(v - __bfloat162float(hi));
        }
        __syncthreads();
#pragma unroll
        for (int ks = 0; ks < 4; ks++) {
            int k0h = ks * 8;
            uint32_t ah[2][4], al[2][4];
#pragma unroll
            for (int mi = 0; mi < 2; mi++) {
                int rb = wy * 32 + mi * 16;
                ah[mi][0] = sAhi[(rb + g) * AST + k0h + tg];
                ah[mi][1] = sAhi[(rb + g + 8) * AST + k0h + tg];
                ah[mi][2] = sAhi[(rb + g) * AST + k0h + tg + 4];
                ah[mi][3] = sAhi[(rb + g + 8) * AST + k0h + tg + 4];
                al[mi][0] = sAlo[(rb + g) * AST + k0h + tg];
                al[mi][1] = sAlo[(rb + g + 8) * AST + k0h + tg];
                al[mi][2] = sAlo[(rb + g) * AST + k0h + tg + 4];
                al[mi][3] = sAlo[(rb + g + 8) * AST + k0h + tg + 4];
            }
#pragma unroll
            for (int jj = 0; jj < 8; jj++) {
                int n = (wx * 8 + jj) * 8 + g;
                const uint2* wp = g_w2 + n * 128 + ch * 32 + k0h + tg;
                uint2 b0 = wp[0];
                uint2 b1 = wp[4];
#pragma unroll
                for (int mi = 0; mi < 2; mi++) {
                    MMA3(c[mi][jj], ah[mi], al[mi], b0.x, b1.x, b0.y, b1.y);
                }
            }
        }
    }
    __syncthreads();
    // write C tile to sH (overlay)
#pragma unroll
    for (int mi = 0; mi < 2; mi++) {
#pragma unroll
        for (int jj = 0; jj < 8; jj++) {
            int row = wy * 32 + mi * 16 + g;
            int col = (wx * 8 + jj) * 8 + tg * 2;
            *(float2*)&sH[row * HST + col]       = make_float2(c[mi][jj][0], c[mi][jj][1]);
            *(float2*)&sH[(row + 8) * HST + col] = make_float2(c[mi][jj][2], c[mi][jj][3]);
        }
    }
    __syncthreads();
    // per-column epilogue: bias + BN2 stats + run-length pool
    int t = tid;
    float b = bc2[t] + bl2[t];
    float sum = 0.f, ssq = 0.f, seg = 0.f;
    int cg = sb[0];
    int nrows = min(64, N_NODES - i0);
    for (int r = 0; r < nrows; r++) {
        float v = sH[r * HST + t] + b;
        sum += v;
        ssq += v * v;
        int gId = sb[r];
        if (gId != cg) {
            atomicAdd(&g_pool[cg * H + t], seg);
            seg = 0.f;
            cg = gId;
        }
        seg += v;
    }
    atomicAdd(&g_pool[cg * H + t], seg);
    atomicAdd(&g_bn2[t], sum);
    atomicAdd(&g_bn2[H + t], ssq);
}

// ---------------- pooling + head ----------------

__global__ void k_gcnt(const int* __restrict__ batch) {
    __shared__ int sh[N_GRAPHS];
    if (threadIdx.x < N_GRAPHS) sh[threadIdx.x] = 0;
    __syncthreads();
    int i = blockIdx.x * blockDim.x + threadIdx.x;
    if (i < N_NODES) atomicAdd(&sh[batch[i]], 1);
    __syncthreads();
    if (threadIdx.x < N_GRAPHS && sh[threadIdx.x])
        atomicAdd(&g_gcnt[threadIdx.x], sh[threadIdx.x]);
}

__global__ void __launch_bounds__(H) k_head(const float* __restrict__ W3,
                                            const float* __restrict__ b3,
                                            float* __restrict__ out) {
    __shared__ float sp[H];
    int g = blockIdx.x;
    int f = threadIdx.x;
    int cnt = g_gcnt[g];
    float pooled = 0.f;
    if (cnt > 0)
        pooled = fmaf(g_pool[g * H + f] / (float)cnt, g_s2[f], g_t2[f]);
    sp[f] = pooled;
    __syncthreads();
    if (f < N_CLASSES) {
        float o = b3[f];
#pragma unroll 8
        for (int k = 0; k < H; k++) o = fmaf(sp[k], W3[k * N_CLASSES + f], o);
        out[g * N_CLASSES + f] = o;
    }
}

// ---------------- host launch ----------------
extern "C" void kernel_launch(void* const* d_in, const int* in_sizes, int n_in,
                              void* d_out, int out_size) {
    const float* x   = (const float*)d_in[0];
    const int*   ei  = (const int*)d_in[1];
    const int*   bat = (const int*)d_in[2];
    const float* Wc1 = (const float*)d_in[3];
    const float* bc1 = (const float*)d_in[4];
    const float* Wl1 = (const float*)d_in[5];
    const float* bl1 = (const float*)d_in[6];
    const float* g1  = (const float*)d_in[7];
    const float* be1 = (const float*)d_in[8];
    const float* Wc2 = (const float*)d_in[9];
    const float* bc2 = (const float*)d_in[10];
    const float* Wl2 = (const float*)d_in[11];
    const float* bl2 = (const float*)d_in[12];
    const float* g2  = (const float*)d_in[13];
    const float* be2 = (const float*)d_in[14];
    const float* W3  = (const float*)d_in[15];
    const float* b3  = (const float*)d_in[16];
    float* out = (float*)d_out;

    const int* src = ei;
    const int* dst = ei + N_EDGES;

    void *p_deg, *p_bn1, *p_bn2, *p_gcnt, *p_pool;
    void *p_s1, *p_t1, *p_s2, *p_t2;
    cudaGetSymbolAddress(&p_deg,  g_deg);
    cudaGetSymbolAddress(&p_bn1,  g_bn1);
    cudaGetSymbolAddress(&p_bn2,  g_bn2);
    cudaGetSymbolAddress(&p_gcnt, g_gcnt);
    cudaGetSymbolAddress(&p_pool, g_pool);
    cudaGetSymbolAddress(&p_s1, g_s1);
    cudaGetSymbolAddress(&p_t1, g_t1);
    cudaGetSymbolAddress(&p_s2, g_s2);
    cudaGetSymbolAddress(&p_t2, g_t2);

    cudaMemsetAsync(p_deg,  0, N_NODES * sizeof(int), 0);
    cudaMemsetAsync(p_bn1,  0, 2 * H * sizeof(float), 0);
    cudaMemsetAsync(p_bn2,  0, 2 * H * sizeof(float), 0);
    cudaMemsetAsync(p_gcnt, 0, N_GRAPHS * sizeof(int), 0);
    cudaMemsetAsync(p_pool, 0, N_GRAPHS * H * sizeof(float), 0);

    k_deg<<<(N_EDGES + 255) / 256, 256>>>(dst);
    k_chunksum<<<NCHUNK, 1024>>>();
    k_bscan<<<1, 128>>>();
    k_finoff<<<NCHUNK, 1024>>>();
    k_dinv<<<(N_NODES + 255) / 256, 256>>>();
    k_fill<<<(N_EDGES + 255) / 256, 256>>>(src, dst);
    k_gather1<<<((size_t)N_NODES * 32 + 255) / 256, 256>>>(x);
    k_layer1<<<(N_NODES + NPB - 1) / NPB, H>>>(x, Wc1, bc1, Wl1, bl1);
    k_bnfin<<<1, H>>>((const float*)p_bn1, g1, be1, (float*)p_s1, (float*)p_t1);
    k_wprep<<<(128 * 128 + 255) / 256, 256>>>(Wc2, Wl2);
    k_gather2<<<((size_t)N_NODES * 32 + 255) / 256, 256>>>();
    k_gemm2<<<(N_NODES + 63) / 64, 128>>>(bc2, bl2, bat);
    k_bnfin<<<1, H>>>((const float*)p_bn2, g2, be2, (float*)p_s2, (float*)p_t2);
    k_gcnt<<<(N_NODES + 255) / 256, 256>>>(bat);
    k_head<<<N_GRAPHS, H>>>(W3, b3, out);
}

// round 8
// speedup vs baseline: 2.3138x; 1.3420x over previous
#include <cuda_runtime.h>
#include <cuda_bf16.h>
#include <cuda_fp16.h>
#include <cstdint>

#define N_NODES 100000
#define N_EDGES 3200000
#define H 128
#define N_GRAPHS 128
#define N_CLASSES 10
#define EPSBN 1e-5f
#define NCHUNK 98               // ceil(100000/1024)

// ---------------- device scratch (static, no allocation) ----------------
__device__ int   g_deg[N_NODES];
__device__ int   g_off[N_NODES + 1];
__device__ int   g_cur[N_NODES];
__device__ int   g_bsum[NCHUNK];
__device__ int   g_bpre[NCHUNK];
__device__ int   g_csrc[N_EDGES];                               // CSR-by-dst src ids
__device__ float g_dinv[N_NODES];                               // rsqrt(deg+1)
__device__ float g_rdinv[N_NODES];                              // sqrt(deg+1) = 1/dinv
__device__ float g_acc1[N_NODES];                               // sum dinv[s]*x[s]
__device__ float g_sdin[N_NODES];                               // sum dinv[s]
__device__ __align__(16) __half g_h1s[(size_t)N_NODES * H];     // dinv[i]*relu(h1) fp16
__device__ __align__(16) __half g_aggh[(size_t)N_NODES * H];    // sum_s h1s[s] fp16
__device__ __align__(8) uint2 g_w2[128 * 128];                  // [n][kword]: {hi,lo} bf16x2
__device__ float g_bn1[2 * H];
__device__ float g_bn2[2 * H];
__device__ float g_s1[H], g_t1[H], g_s2[H], g_t2[H];
__device__ float g_pool[N_GRAPHS * H];
__device__ int   g_gcnt[N_GRAPHS];

// ---------------- CSR build ----------------

__global__ void k_deg(const int* __restrict__ dst) {
    int e = blockIdx.x * blockDim.x + threadIdx.x;
    if (e < N_EDGES) atomicAdd(&g_deg[dst[e]], 1);
}

__global__ void __launch_bounds__(1024) k_chunksum() {
    __shared__ int ss[1024];
    int t = threadIdx.x;
    int i = blockIdx.x * 1024 + t;
    int v = (i < N_NODES) ? g_deg[i] : 0;
    ss[t] = v;
    __syncthreads();
    for (int o = 1; o < 1024; o <<= 1) {
        int u = (t >= o) ? ss[t - o] : 0;
        __syncthreads();
        ss[t] += u;
        __syncthreads();
    }
    if (i < N_NODES) g_off[i] = ss[t] - v;
    if (t == 1023) g_bsum[blockIdx.x] = ss[1023];
}

__global__ void __launch_bounds__(128) k_bscan() {
    __shared__ int ss[128];
    int t = threadIdx.x;
    int v = (t < NCHUNK) ? g_bsum[t] : 0;
    ss[t] = v;
    __syncthreads();
    for (int o = 1; o < 128; o <<= 1) {
        int u = (t >= o) ? ss[t - o] : 0;
        __syncthreads();
        ss[t] += u;
        __syncthreads();
    }
    if (t < NCHUNK) g_bpre[t] = ss[t] - v;
    if (t == NCHUNK - 1) g_off[N_NODES] = ss[t];
}

// finalize offsets + cursor + dinv/rdinv in one pass
__global__ void __launch_bounds__(1024) k_finoff() {
    int i = blockIdx.x * 1024 + threadIdx.x;
    if (i < N_NODES) {
        int o = g_off[i] + g_bpre[blockIdx.x];
        g_off[i] = o;
        g_cur[i] = o;
        float dp1 = (float)(g_deg[i] + 1);
        g_dinv[i]  = rsqrtf(dp1);
        g_rdinv[i] = sqrtf(dp1);
    }
}

__global__ void k_fill(const int* __restrict__ src, const int* __restrict__ dst) {
    int e = blockIdx.x * blockDim.x + threadIdx.x;
    if (e >= N_EDGES) return;
    int slot = atomicAdd(&g_cur[dst[e]], 1);
    g_csrc[slot] = src[e];
}

// ---------------- layer 1 ----------------

// warp per node: acc1[d] = sum dinv[s]*x[s], sdin[d] = sum dinv[s]
__global__ void k_gather1(const float* __restrict__ x) {
    int node = (blockIdx.x * blockDim.x + threadIdx.x) >> 5;
    int lane = threadIdx.x & 31;
    if (node >= N_NODES) return;
    int e0 = g_off[node], e1 = g_off[node + 1];
    float a = 0.f, sd = 0.f;
    for (int e = e0 + lane; e < e1; e += 32) {
        int s = g_csrc[e];
        float w = __ldg(&g_dinv[s]);
        a = fmaf(w, __ldg(&x[s]), a);
        sd += w;
    }
#pragma unroll
    for (int o = 16; o > 0; o >>= 1) {
        a  += __shfl_down_sync(0xffffffffu, a, o);
        sd += __shfl_down_sync(0xffffffffu, sd, o);
    }
    if (lane == 0) { g_acc1[node] = a; g_sdin[node] = sd; }
}

// layer1 transform; stores h1s = dinv[i]*relu(h) in fp16; BN1 stats on raw h
#define NPB 128
__global__ void __launch_bounds__(H) k_layer1(const float* __restrict__ x,
                                              const float* __restrict__ Wc1,
                                              const float* __restrict__ bc1,
                                              const float* __restrict__ Wl1,
                                              const float* __restrict__ bl1) {
    int f = threadIdx.x;
    float wc = Wc1[f], wl = Wl1[f], b = bc1[f] + bl1[f];
    float sum = 0.f, ssq = 0.f;
    int i0 = blockIdx.x * NPB;
    for (int r = 0; r < NPB; r++) {
        int i = i0 + r;
        if (i >= N_NODES) break;
        float di = g_dinv[i];
        float xi = x[i];
        float a = di * g_acc1[i] + di * di * xi;
        float h = fmaf(a, wc, fmaf(xi, wl, b));
        h = fmaxf(h, 0.f);
        g_h1s[(size_t)i * H + f] = __float2half_rn(di * h);
        sum += h;
        ssq += h * h;
    }
    atomicAdd(&g_bn1[f], sum);
    atomicAdd(&g_bn1[H + f], ssq);
}

__global__ void k_bnfin(const float* __restrict__ sums,
                        const float* __restrict__ gamma,
                        const float* __restrict__ beta,
                        float* __restrict__ s_out, float* __restrict__ t_out) {
    int f = threadIdx.x;
    float inv_n = 1.0f / (float)N_NODES;
    float mu = sums[f] * inv_n;
    float var = sums[H + f] * inv_n - mu * mu;
    float s = gamma[f] * rsqrtf(var + EPSBN);
    s_out[f] = s;
    t_out[f] = beta[f] - mu * s;
}

// ---------------- layer 2 aggregation (warp per node, fp16 rows, fp32 accum) ----------------

__global__ void k_gather2() {
    int node = (blockIdx.x * blockDim.x + threadIdx.x) >> 5;
    int lane = threadIdx.x & 31;
    if (node >= N_NODES) return;
    int e0 = g_off[node], e1 = g_off[node + 1];
    float ax = 0.f, ay = 0.f, az = 0.f, aw = 0.f;
    if (e0 < e1) {
        int s = g_csrc[e0];
        for (int e = e0; e < e1; e++) {
            int sn = (e + 1 < e1) ? __ldg(&g_csrc[e + 1]) : s;    // prefetch next src
            uint2 hv = *(const uint2*)(g_h1s + (size_t)s * H + lane * 4);
            __half2 p0 = *(__half2*)&hv.x;
            __half2 p1 = *(__half2*)&hv.y;
            float2 f0 = __half22float2(p0);
            float2 f1 = __half22float2(p1);
            ax += f0.x; ay += f0.y; az += f1.x; aw += f1.y;
            s = sn;
        }
    }
    __half2 o0 = __floats2half2_rn(ax, ay);
    __half2 o1 = __floats2half2_rn(az, aw);
    uint2 out;
    out.x = *(uint32_t*)&o0;
    out.y = *(uint32_t*)&o1;
    *(uint2*)(g_aggh + (size_t)node * H + lane * 4) = out;
}

// ---------------- W prep: interleaved bf16 hi/lo split ----------------

__device__ __forceinline__ uint32_t pack_bf2(__nv_bfloat16 a, __nv_bfloat16 b) {
    __nv_bfloat162 p; p.x = a; p.y = b;
    return *(uint32_t*)&p;
}

__global__ void k_wprep(const float* __restrict__ Wc2, const float* __restrict__ Wl2) {
    int idx = blockIdx.x * blockDim.x + threadIdx.x;   // 128 n * 128 kwords
    if (idx >= 128 * 128) return;
    int n = idx >> 7, kw = idx & 127;
    int k0 = kw * 2, k1 = kw * 2 + 1;
    float v0 = (k0 < 128) ? Wc2[k0 * 128 + n] : Wl2[(k0 - 128) * 128 + n];
    float v1 = (k1 < 128) ? Wc2[k1 * 128 + n] : Wl2[(k1 - 128) * 128 + n];
    __nv_bfloat16 h0 = __float2bfloat16_rn(v0);
    __nv_bfloat16 h1v = __float2bfloat16_rn(v1);
    __nv_bfloat16 l0 = __float2bfloat16_rn(v0 - __bfloat162float(h0));
    __nv_bfloat16 l1 = __float2bfloat16_rn(v1 - __bfloat162float(h1v));
    g_w2[n * 128 + kw] = make_uint2(pack_bf2(h0, h1v), pack_bf2(l0, l1));
}

// ---------------- fused layer-2 GEMM (split-bf16 mma) + BN2 + pool ----------------
// Block: 128 threads (4 warps as 2 M-pairs x 2 N-halves). Tile: 64 nodes x 128 feats.
// K=256 in 4 chunks of 64. A[:,0:128)=A1 (conv), [128:256)=A2 (hn1). C = A @ W^T.

#define AST 36                     // A row stride in b32 (64 bf16 + pad)
#define HST 132                    // sH row stride in f32

#define MMA3(cc, ah, al, bh0, bh1, bl0, bl1)                                   \
    asm volatile("mma.sync.aligned.m16n8k16.row.col.f32.bf16.bf16.f32 "        \
        "{%0,%1,%2,%3}, {%4,%5,%6,%7}, {%8,%9}, {%0,%1,%2,%3};"                \
        : "+f"(cc[0]), "+f"(cc[1]), "+f"(cc[2]), "+f"(cc[3])                   \
        : "r"(ah[0]), "r"(ah[1]), "r"(ah[2]), "r"(ah[3]), "r"(bh0), "r"(bh1)); \
    asm volatile("mma.sync.aligned.m16n8k16.row.col.f32.bf16.bf16.f32 "        \
        "{%0,%1,%2,%3}, {%4,%5,%6,%7}, {%8,%9}, {%0,%1,%2,%3};"                \
        : "+f"(cc[0]), "+f"(cc[1]), "+f"(cc[2]), "+f"(cc[3])                   \
        : "r"(al[0]), "r"(al[1]), "r"(al[2]), "r"(al[3]), "r"(bh0), "r"(bh1)); \
    asm volatile("mma.sync.aligned.m16n8k16.row.col.f32.bf16.bf16.f32 "        \
        "{%0,%1,%2,%3}, {%4,%5,%6,%7}, {%8,%9}, {%0,%1,%2,%3};"                \
        : "+f"(cc[0]), "+f"(cc[1]), "+f"(cc[2]), "+f"(cc[3])                   \
        : "r"(ah[0]), "r"(ah[1]), "r"(ah[2]), "r"(ah[3]), "r"(bl0), "r"(bl1));

__global__ void __launch_bounds__(128) k_gemm2(const float* __restrict__ bc2,
                                               const float* __restrict__ bl2,
                                               const int* __restrict__ bat) {
    __shared__ __align__(16) char smem_raw[64 * HST * 4];       // 33792 B union
    uint32_t* sAhi = (uint32_t*)smem_raw;                       // [64][AST]
    uint32_t* sAlo = sAhi + 64 * AST;
    __nv_bfloat16* sAhi_b = (__nv_bfloat16*)sAhi;
    __nv_bfloat16* sAlo_b = (__nv_bfloat16*)sAlo;
    float* sH = (float*)smem_raw;                               // overlay after mma
    __shared__ float ss1[H], st1[H];
    __shared__ int sb[64];

    int tid = threadIdx.x;
    int lane = tid & 31;
    int warp = tid >> 5;
    int g = lane >> 2, tg = lane & 3;
    int wx = warp & 1, wy = warp >> 1;      // wx: N-half, wy: M-pair
    int i0 = blockIdx.x * 64;

    ss1[tid] = g_s1[tid];
    st1[tid] = g_t1[tid];
    if (tid < 64) {
        int i = i0 + tid;
        sb[tid] = (i < N_NODES) ? bat[i] : 0;
    }

    float c[2][8][4];
#pragma unroll
    for (int mi = 0; mi < 2; mi++)
#pragma unroll
        for (int jj = 0; jj < 8; jj++)
#pragma unroll
            for (int q = 0; q < 4; q++) c[mi][jj][q] = 0.f;

    for (int ch = 0; ch < 4; ch++) {
        int kc0 = ch * 64;
        __syncthreads();
        // stage A chunk, split hi/lo
        for (int idx = tid; idx < 64 * 64; idx += 128) {
            int r = idx >> 6, fc = idx & 63;
            int i = i0 + r;
            int f = kc0 + fc;
            float v = 0.f;
            if (i < N_NODES) {
                if (f < 128) {
                    // hn1 = h1*s1+t1, h1 = h1s*rdinv
                    float h1 = __half2float(g_h1s[(size_t)i * H + f]) * g_rdinv[i];
                    float hn = fmaf(h1, ss1[f], st1[f]);
                    float di = g_dinv[i];
                    float agg = __half2float(g_aggh[(size_t)i * H + f]);
                    v = di * (fmaf(ss1[f], agg, st1[f] * g_sdin[i]) + di * hn);
                } else {
                    int ff = f - 128;
                    float h1 = __half2float(g_h1s[(size_t)i * H + ff]) * g_rdinv[i];
                    v = fmaf(h1, ss1[ff], st1[ff]);
                }
            }
            __nv_bfloat16 hi = __float2bfloat16_rn(v);
            sAhi_b[r * (AST * 2) + fc] = hi;
            sAlo_b[r * (AST * 2) + fc] = __float2bfloat16_rn(v - __bfloat162float(hi));
        }
        __syncthreads();
#pragma unroll
        for (int ks = 0; ks < 4; ks++) {
            int k0h = ks * 8;
            uint32_t ah[2][4], al[2][4];
#pragma unroll
            for (int mi = 0; mi < 2; mi++) {
                int rb = wy * 32 + mi * 16;
                ah[mi][0] = sAhi[(rb + g) * AST + k0h + tg];
                ah[mi][1] = sAhi[(rb + g + 8) * AST + k0h + tg];
                ah[mi][2] = sAhi[(rb + g) * AST + k0h + tg + 4];
                ah[mi][3] = sAhi[(rb + g + 8) * AST + k0h + tg + 4];
                al[mi][0] = sAlo[(rb + g) * AST + k0h + tg];
                al[mi][1] = sAlo[(rb + g + 8) * AST + k0h + tg];
                al[mi][2] = sAlo[(rb + g) * AST + k0h + tg + 4];
                al[mi][3] = sAlo[(rb + g + 8) * AST + k0h + tg + 4];
            }
#pragma unroll
            for (int jj = 0; jj < 8; jj++) {
                int n = (wx * 8 + jj) * 8 + g;
                const uint2* wp = g_w2 + n * 128 + ch * 32 + k0h + tg;
                uint2 b0 = wp[0];
                uint2 b1 = wp[4];
#pragma unroll
                for (int mi = 0; mi < 2; mi++) {
                    MMA3(c[mi][jj], ah[mi], al[mi], b0.x, b1.x, b0.y, b1.y);
                }
            }
        }
    }
    __syncthreads();
    // write C tile to sH (overlay)
#pragma unroll
    for (int mi = 0; mi < 2; mi++) {
#pragma unroll
        for (int jj = 0; jj < 8; jj++) {
            int row = wy * 32 + mi * 16 + g;
            int col = (wx * 8 + jj) * 8 + tg * 2;
            *(float2*)&sH[row * HST + col]       = make_float2(c[mi][jj][0], c[mi][jj][1]);
            *(float2*)&sH[(row + 8) * HST + col] = make_float2(c[mi][jj][2], c[mi][jj][3]);
        }
    }
    __syncthreads();
    // per-column epilogue: bias + BN2 stats + run-length pool
    int t = tid;
    float b = bc2[t] + bl2[t];
    float sum = 0.f, ssq = 0.f, seg = 0.f;
    int cg = sb[0];
    int nrows = min(64, N_NODES - i0);
    for (int r = 0; r < nrows; r++) {
        float v = sH[r * HST + t] + b;
        sum += v;
        ssq += v * v;
        int gId = sb[r];
        if (gId != cg) {
            atomicAdd(&g_pool[cg * H + t], seg);
            seg = 0.f;
            cg = gId;
        }
        seg += v;
    }
    atomicAdd(&g_pool[cg * H + t], seg);
    atomicAdd(&g_bn2[t], sum);
    atomicAdd(&g_bn2[H + t], ssq);
}

// ---------------- pooling + head ----------------

__global__ void k_gcnt(const int* __restrict__ batch) {
    __shared__ int sh[N_GRAPHS];
    if (threadIdx.x < N_GRAPHS) sh[threadIdx.x] = 0;
    __syncthreads();
    int i = blockIdx.x * blockDim.x + threadIdx.x;
    if (i < N_NODES) atomicAdd(&sh[batch[i]], 1);
    __syncthreads();
    if (threadIdx.x < N_GRAPHS && sh[threadIdx.x])
        atomicAdd(&g_gcnt[threadIdx.x], sh[threadIdx.x]);
}

__global__ void __launch_bounds__(H) k_head(const float* __restrict__ W3,
                                            const float* __restrict__ b3,
                                            float* __restrict__ out) {
    __shared__ float sp[H];
    int g = blockIdx.x;
    int f = threadIdx.x;
    int cnt = g_gcnt[g];
    float pooled = 0.f;
    if (cnt > 0)
        pooled = fmaf(g_pool[g * H + f] / (float)cnt, g_s2[f], g_t2[f]);
    sp[f] = pooled;
    __syncthreads();
    if (f < N_CLASSES) {
        float o = b3[f];
#pragma unroll 8
        for (int k = 0; k < H; k++) o = fmaf(sp[k], W3[k * N_CLASSES + f], o);
        out[g * N_CLASSES + f] = o;
    }
}

// ---------------- host launch ----------------
extern "C" void kernel_launch(void* const* d_in, const int* in_sizes, int n_in,
                              void* d_out, int out_size) {
    const float* x   = (const float*)d_in[0];
    const int*   ei  = (const int*)d_in[1];
    const int*   bat = (const int*)d_in[2];
    const float* Wc1 = (const float*)d_in[3];
    const float* bc1 = (const float*)d_in[4];
    const float* Wl1 = (const float*)d_in[5];
    const float* bl1 = (const float*)d_in[6];
    const float* g1  = (const float*)d_in[7];
    const float* be1 = (const float*)d_in[8];
    const float* Wc2 = (const float*)d_in[9];
    const float* bc2 = (const float*)d_in[10];
    const float* Wl2 = (const float*)d_in[11];
    const float* bl2 = (const float*)d_in[12];
    const float* g2  = (const float*)d_in[13];
    const float* be2 = (const float*)d_in[14];
    const float* W3  = (const float*)d_in[15];
    const float* b3  = (const float*)d_in[16];
    float* out = (float*)d_out;

    const int* src = ei;
    const int* dst = ei + N_EDGES;

    void *p_deg, *p_bn1, *p_bn2, *p_gcnt, *p_pool;
    void *p_s1, *p_t1, *p_s2, *p_t2;
    cudaGetSymbolAddress(&p_deg,  g_deg);
    cudaGetSymbolAddress(&p_bn1,  g_bn1);
    cudaGetSymbolAddress(&p_bn2,  g_bn2);
    cudaGetSymbolAddress(&p_gcnt, g_gcnt);
    cudaGetSymbolAddress(&p_pool, g_pool);
    cudaGetSymbolAddress(&p_s1, g_s1);
    cudaGetSymbolAddress(&p_t1, g_t1);
    cudaGetSymbolAddress(&p_s2, g_s2);
    cudaGetSymbolAddress(&p_t2, g_t2);

    cudaMemsetAsync(p_deg,  0, N_NODES * sizeof(int), 0);
    cudaMemsetAsync(p_bn1,  0, 2 * H * sizeof(float), 0);
    cudaMemsetAsync(p_bn2,  0, 2 * H * sizeof(float), 0);
    cudaMemsetAsync(p_gcnt, 0, N_GRAPHS * sizeof(int), 0);
    cudaMemsetAsync(p_pool, 0, N_GRAPHS * H * sizeof(float), 0);

    k_deg<<<(N_EDGES + 255) / 256, 256>>>(dst);
    k_chunksum<<<NCHUNK, 1024>>>();
    k_bscan<<<1, 128>>>();
    k_finoff<<<NCHUNK, 1024>>>();
    k_fill<<<(N_EDGES + 255) / 256, 256>>>(src, dst);
    k_gather1<<<((size_t)N_NODES * 32 + 255) / 256, 256>>>(x);
    k_layer1<<<(N_NODES + NPB - 1) / NPB, H>>>(x, Wc1, bc1, Wl1, bl1);
    k_bnfin<<<1, H>>>((const float*)p_bn1, g1, be1, (float*)p_s1, (float*)p_t1);
    k_wprep<<<(128 * 128 + 255) / 256, 256>>>(Wc2, Wl2);
    k_gather2<<<((size_t)N_NODES * 32 + 255) / 256, 256>>>();
    k_gemm2<<<(N_NODES + 63) / 64, 128>>>(bc2, bl2, bat);
    k_bnfin<<<1, H>>>((const float*)p_bn2, g2, be2, (float*)p_s2, (float*)p_t2);
    k_gcnt<<<(N_NODES + 255) / 256, 256>>>(bat);
    k_head<<<N_GRAPHS, H>>>(W3, b3, out);
}